// round 14
// baseline (speedup 1.0000x reference)
#include <cuda_runtime.h>
#include <cuda_bf16.h>
#include <cstdint>

typedef unsigned long long ull;

#define BB    64
#define TT    512
#define MMM   (BB * TT)

// ---------------------------------------------------------------------------
// Scratch (static __device__ arrays -- allocation-free)
// ---------------------------------------------------------------------------
__device__ float g_xg[2u * MMM * 512];
__device__ float g_xgB[BB * 512];
__device__ float g_ya[MMM * 256];
__device__ float g_yb[MMM * 256];
__device__ float g_ylast[BB * 256];
__device__ __nv_bfloat16 g_xc[(size_t)MMM * 768];   // split X  [M][3K]
__device__ __nv_bfloat16 g_wc[1024 * 768];          // split W  [N][3K]
__device__ float g_bias[1024];

// ---------------------------------------------------------------------------
// f32x2 helpers (LSTM / gemv)
// ---------------------------------------------------------------------------
__device__ __forceinline__ ull pk2(float lo, float hi) {
    ull r; asm("mov.b64 %0, {%1, %2};" : "=l"(r) : "f"(lo), "f"(hi)); return r;
}
__device__ __forceinline__ ull fma2(ull a, ull b, ull c) {
    ull d; asm("fma.rn.f32x2 %0, %1, %2, %3;" : "=l"(d) : "l"(a), "l"(b), "l"(c)); return d;
}
__device__ __forceinline__ ull add2(ull a, ull b) {
    ull d; asm("add.rn.f32x2 %0, %1, %2;" : "=l"(d) : "l"(a), "l"(b)); return d;
}
__device__ __forceinline__ float2 upk2(ull v) {
    float2 f; asm("mov.b64 {%0, %1}, %2;" : "=f"(f.x), "=f"(f.y) : "l"(v)); return f;
}
__device__ __forceinline__ float hsum2(ull v) { float2 f = upk2(v); return f.x + f.y; }

__device__ __forceinline__ float tanh_a(float x) {
    float r; asm("tanh.approx.f32 %0, %1;" : "=f"(r) : "f"(x)); return r;
}
__device__ __forceinline__ float sig_a(float x) {
    return fmaf(0.5f, tanh_a(0.5f * x), 0.5f);
}

__device__ __forceinline__ uint32_t smem_u32(const void* p) {
    uint32_t a;
    asm("{ .reg .u64 t; cvta.to.shared.u64 t, %1; cvt.u32.u64 %0, t; }" : "=r"(a) : "l"(p));
    return a;
}

// pack 8 floats -> (hi uint4, lo uint4) of bf16
__device__ __forceinline__ void split8(const float* v, uint4& hiP, uint4& loP) {
    __nv_bfloat162 h[4], l[4];
#pragma unroll
    for (int q = 0; q < 4; q++) {
        __nv_bfloat16 h0 = __float2bfloat16(v[2 * q]);
        __nv_bfloat16 h1 = __float2bfloat16(v[2 * q + 1]);
        __nv_bfloat16 l0 = __float2bfloat16(v[2 * q]     - __bfloat162float(h0));
        __nv_bfloat16 l1 = __float2bfloat16(v[2 * q + 1] - __bfloat162float(h1));
        h[q] = __nv_bfloat162(h0, h1);
        l[q] = __nv_bfloat162(l0, l1);
    }
    hiP = *reinterpret_cast<uint4*>(h);
    loP = *reinterpret_cast<uint4*>(l);
}

// ---------------------------------------------------------------------------
// conv_x0: fused embedding gather + bf16 split for layer 0 (K=128).
//   out[m][0:K]=hi, [K:2K]=hi, [2K:3K]=lo
// ---------------------------------------------------------------------------
__global__ void conv_x0(const int* __restrict__ Xtok,
                        const float* __restrict__ emb,
                        __nv_bfloat16* __restrict__ out) {
    int i = blockIdx.x * 256 + threadIdx.x;     // MMM*16 threads
    int m  = i >> 4;
    int k8 = (i & 15) << 3;
    int tok = Xtok[m];
    float v[8];
    *reinterpret_cast<float4*>(v)     = *reinterpret_cast<const float4*>(&emb[(size_t)tok * 128 + k8]);
    *reinterpret_cast<float4*>(v + 4) = *reinterpret_cast<const float4*>(&emb[(size_t)tok * 128 + k8 + 4]);
    uint4 hiP, loP;
    split8(v, hiP, loP);
    __nv_bfloat16* base = out + (size_t)m * 384;
    *reinterpret_cast<uint4*>(base + k8)       = hiP;
    *reinterpret_cast<uint4*>(base + 128 + k8) = hiP;
    *reinterpret_cast<uint4*>(base + 256 + k8) = loP;
}

// ---------------------------------------------------------------------------
// conv_x: vectorized fp32 [M][256] -> bf16 split [M][768]  (layers 1,2)
// ---------------------------------------------------------------------------
__global__ void conv_x(const float* __restrict__ in, __nv_bfloat16* __restrict__ out) {
    int i = blockIdx.x * 256 + threadIdx.x;     // MMM*32 threads
    int m  = i >> 5;
    int k8 = (i & 31) << 3;
    float v[8];
    *reinterpret_cast<float4*>(v)     = *reinterpret_cast<const float4*>(&in[(size_t)m * 256 + k8]);
    *reinterpret_cast<float4*>(v + 4) = *reinterpret_cast<const float4*>(&in[(size_t)m * 256 + k8 + 4]);
    uint4 hiP, loP;
    split8(v, hiP, loP);
    __nv_bfloat16* base = out + (size_t)m * 768;
    *reinterpret_cast<uint4*>(base + k8)       = hiP;
    *reinterpret_cast<uint4*>(base + 256 + k8) = hiP;
    *reinterpret_cast<uint4*>(base + 512 + k8) = loP;
}

// ---------------------------------------------------------------------------
// conv_w: fp32 [N][K] -> bf16 split [N][3K] = [hi | lo | hi]  (scalar, tiny)
// ---------------------------------------------------------------------------
__global__ void conv_w(const float* __restrict__ in, __nv_bfloat16* __restrict__ out,
                       int kshift) {
    int i = blockIdx.x * 256 + threadIdx.x;
    int K = 1 << kshift;
    int n = i >> kshift;
    int k = i & (K - 1);
    float v = in[i];
    __nv_bfloat16 hi = __float2bfloat16(v);
    __nv_bfloat16 lo = __float2bfloat16(v - __bfloat162float(hi));
    size_t base = (size_t)n * 3 * K;
    out[base + k]         = hi;
    out[base + K + k]     = lo;
    out[base + 2 * K + k] = hi;
}

__global__ void bias_k(const float* __restrict__ bi, const float* __restrict__ bh,
                       float* __restrict__ out) {
    int i = blockIdx.x * 256 + threadIdx.x;
    out[i] = bi[i] + bh[i];
}

// ---------------------------------------------------------------------------
// Kernel 2: tensor-core GEMM via mma.sync (bf16 -> f32)  [unchanged from R13]
// ---------------------------------------------------------------------------
#define TILE_BYTES 10240   /* 128 rows x 80 B */

#define LDSM4(r0, r1, r2, r3, addr) \
    asm volatile("ldmatrix.sync.aligned.m8n8.x4.shared.b16 {%0,%1,%2,%3}, [%4];" \
        : "=r"(r0), "=r"(r1), "=r"(r2), "=r"(r3) : "r"(addr))

#define MMA16816(d, a, b0, b1) \
    asm volatile("mma.sync.aligned.m16n8k16.row.col.f32.bf16.bf16.f32 " \
        "{%0,%1,%2,%3}, {%4,%5,%6,%7}, {%8,%9}, {%0,%1,%2,%3};" \
        : "+f"((d)[0]), "+f"((d)[1]), "+f"((d)[2]), "+f"((d)[3]) \
        : "r"((a)[0]), "r"((a)[1]), "r"((a)[2]), "r"((a)[3]), "r"(b0), "r"(b1))

__global__ __launch_bounds__(256, 2)
void gemm_mma(const __nv_bfloat16* __restrict__ Xc,
              const __nv_bfloat16* __restrict__ Wc,
              const float* __restrict__ bias,
              float* __restrict__ C,
              int K3, int NC) {
    __shared__ __align__(16) char smA[2][TILE_BYTES];
    __shared__ __align__(16) char smB[2][TILE_BYTES];

    const int tid = threadIdx.x;
    const int w  = tid >> 5, L = tid & 31;
    const int wm = w >> 2,  wn = w & 3;
    const int g  = L >> 3,  r  = L & 7;
    const int m0 = blockIdx.y * 128, n0 = blockIdx.x * 128;

    const uint32_t aSB = smem_u32(smA);
    const uint32_t bSB = smem_u32(smB);

    uint32_t aoff[4][2], boff[2][2];
#pragma unroll
    for (int i = 0; i < 4; i++)
#pragma unroll
        for (int h = 0; h < 2; h++)
            aoff[i][h] = (uint32_t)((wm * 64 + i * 16 + (g & 1) * 8 + r) * 80
                                    + (g >> 1) * 16 + h * 32);
#pragma unroll
    for (int jj = 0; jj < 2; jj++)
#pragma unroll
        for (int h = 0; h < 2; h++)
            boff[jj][h] = (uint32_t)((wn * 32 + jj * 16 + (g >> 1) * 8 + r) * 80
                                     + (g & 1) * 16 + h * 32);

    const int s0 = tid * 2, s1 = tid * 2 + 1;
    const int row0 = s0 >> 2, u0 = s0 & 3;
    const int row1 = s1 >> 2, u1 = s1 & 3;

    float acc[16][4];
#pragma unroll
    for (int i = 0; i < 16; i++)
#pragma unroll
        for (int q = 0; q < 4; q++) acc[i][q] = 0.f;

    uint4 ar0, ar1, br0, br1;

#define LDG_CHUNK(c)                                                            \
    {                                                                           \
        ar0 = *reinterpret_cast<const uint4*>(Xc + (size_t)(m0 + row0) * K3 + (c) * 32 + u0 * 8); \
        ar1 = *reinterpret_cast<const uint4*>(Xc + (size_t)(m0 + row1) * K3 + (c) * 32 + u1 * 8); \
        br0 = *reinterpret_cast<const uint4*>(Wc + (size_t)(n0 + row0) * K3 + (c) * 32 + u0 * 8); \
        br1 = *reinterpret_cast<const uint4*>(Wc + (size_t)(n0 + row1) * K3 + (c) * 32 + u1 * 8); \
    }

#define STS_CHUNK(b)                                                            \
    {                                                                           \
        *reinterpret_cast<uint4*>(smA[b] + row0 * 80 + u0 * 16) = ar0;          \
        *reinterpret_cast<uint4*>(smA[b] + row1 * 80 + u1 * 16) = ar1;          \
        *reinterpret_cast<uint4*>(smB[b] + row0 * 80 + u0 * 16) = br0;          \
        *reinterpret_cast<uint4*>(smB[b] + row1 * 80 + u1 * 16) = br1;          \
    }

    LDG_CHUNK(0);
    STS_CHUNK(0);
    __syncthreads();
    if (NC > 1) LDG_CHUNK(1);

    for (int c = 0; c < NC; c++) {
        const int b = c & 1;
        const uint32_t aB = aSB + b * TILE_BYTES;
        const uint32_t bO = bSB + b * TILE_BYTES;
#pragma unroll
        for (int h = 0; h < 2; h++) {
            uint32_t af[4][4], bf2[2][4];
#pragma unroll
            for (int i = 0; i < 4; i++)
                LDSM4(af[i][0], af[i][1], af[i][2], af[i][3], aB + aoff[i][h]);
#pragma unroll
            for (int jj = 0; jj < 2; jj++)
                LDSM4(bf2[jj][0], bf2[jj][1], bf2[jj][2], bf2[jj][3], bO + boff[jj][h]);
#pragma unroll
            for (int i = 0; i < 4; i++) {
#pragma unroll
                for (int nj = 0; nj < 4; nj++) {
                    MMA16816(acc[i * 4 + nj], af[i],
                             bf2[nj >> 1][(nj & 1) * 2], bf2[nj >> 1][(nj & 1) * 2 + 1]);
                }
            }
        }
        if (c + 1 < NC) {
            STS_CHUNK((c + 1) & 1);
            if (c + 2 < NC) LDG_CHUNK(c + 2);
            __syncthreads();
        }
    }

#pragma unroll
    for (int i = 0; i < 4; i++) {
#pragma unroll
        for (int nj = 0; nj < 4; nj++) {
            const int mg = m0 + wm * 64 + i * 16 + (L >> 2);
            const int ng = n0 + wn * 32 + nj * 8 + (L & 3) * 2;
            const int dd = ng >> 9;
            const int col = ng & 511;
            const float bv0 = bias[ng], bv1 = bias[ng + 1];
            float* Cd = C + (size_t)dd * MMM * 512;
            float* p0 = &Cd[(size_t)mg * 512 + col];
            float* p1 = &Cd[(size_t)(mg + 8) * 512 + col];
            *reinterpret_cast<float2*>(p0) =
                make_float2(acc[i * 4 + nj][0] + bv0, acc[i * 4 + nj][1] + bv1);
            *reinterpret_cast<float2*>(p1) =
                make_float2(acc[i * 4 + nj][2] + bv0, acc[i * 4 + nj][3] + bv1);
        }
    }
}

// ---------------------------------------------------------------------------
// Kernel 2b: layer-2 backward last-timestep GEMV (fp32, exact)
// ---------------------------------------------------------------------------
__global__ __launch_bounds__(256)
void gemv_last(const float* __restrict__ y,
               const float* __restrict__ Wfull,
               const float* __restrict__ bi,
               const float* __restrict__ bh,
               float* __restrict__ out) {
    __shared__ float xr[256];
    const int b = blockIdx.x;
    const float* x = y + ((size_t)b * TT + (TT - 1)) * 256;
    xr[threadIdx.x] = x[threadIdx.x];
    __syncthreads();
#pragma unroll
    for (int nn = 0; nn < 2; nn++) {
        int n = threadIdx.x + nn * 256;
        const float* wr = Wfull + (size_t)(512 + n) * 256;
        ull s2 = 0ull;
        const ull* xp = reinterpret_cast<const ull*>(xr);
        const ull* wp = reinterpret_cast<const ull*>(wr);
#pragma unroll
        for (int k = 0; k < 128; k++) s2 = fma2(xp[k], wp[k], s2);
        out[(size_t)b * 512 + n] = hsum2(s2) + bi[512 + n] + bh[512 + n];
    }
}

// ---------------------------------------------------------------------------
// Kernel 3: LSTM recurrence. i,f,g weights in regs (96 ull); o-gate HALF in
// regs (16 ull), half streamed from smem (128B/thread/step crossbar).
// ---------------------------------------------------------------------------
#define WO_STRIDE 68
#define WO_FLOATS (256 * WO_STRIDE)
#define RED_OFF   WO_FLOATS
#define HV_OFF    (WO_FLOATS + 2048)
#define LSTM2_SMEM ((HV_OFF + 160) * 4)

__global__ __launch_bounds__(256, 1)
void lstm2(const float* __restrict__ xg,
           const float* __restrict__ xgB,
           const float* __restrict__ whh,
           const float* __restrict__ hx0,
           const float* __restrict__ cx0,
           float* __restrict__ y,
           int final_layer) {
    extern __shared__ float sm[];
    float* Wo_s = sm;
    ull*   red  = reinterpret_cast<ull*>(sm + RED_OFF);
    float* hvec = sm + HV_OFF;

    const int tid = threadIdx.x;
    const int j   = tid & 127;
    const int p   = tid >> 7;
    const int d   = blockIdx.x >> 6;
    const int b   = blockIdx.x & 63;
    const int kb  = p << 6;

    const float* W = whh + (size_t)d * 512 * 128;

    for (int idx = tid; idx < 128 * 128; idx += 256) {
        int rr = idx >> 7, k = idx & 127;
        float v = W[(size_t)(384 + rr) * 128 + k];
        Wo_s[((k >> 6) * 128 + rr) * WO_STRIDE + (k & 63)] = v;
    }

    ull Wi[32], Wf[32], Wg[32], WoR[16];
    {
        const float2* ri = reinterpret_cast<const float2*>(W + (size_t)(0   + j) * 128 + kb);
        const float2* rf = reinterpret_cast<const float2*>(W + (size_t)(128 + j) * 128 + kb);
        const float2* rg = reinterpret_cast<const float2*>(W + (size_t)(256 + j) * 128 + kb);
        const float2* ro = reinterpret_cast<const float2*>(W + (size_t)(384 + j) * 128 + kb);
#pragma unroll
        for (int q = 0; q < 32; q++) {
            float2 a = ri[q]; Wi[q] = pk2(a.x, a.y);
            float2 f = rf[q]; Wf[q] = pk2(f.x, f.y);
            float2 gg = rg[q]; Wg[q] = pk2(gg.x, gg.y);
        }
#pragma unroll
        for (int q = 0; q < 16; q++) {
            float2 o = ro[q]; WoR[q] = pk2(o.x, o.y);
        }
    }

    float c = cx0[(size_t)(d * 64 + b) * 128 + j];
    if (tid < 128) hvec[tid] = hx0[(size_t)(d * 64 + b) * 128 + tid];
    __syncthreads();

    const int t0 = d ? (TT - 1) : 0;
    const int dt = d ? -1 : 1;
    const bool bwd_last = (final_layer && d);
    const int nsteps = bwd_last ? 1 : TT;
    const float* xgb = xg + ((size_t)d * MMM + (size_t)b * TT) * 512;

    float xi = 0.f, xf = 0.f, xgv = 0.f, xo = 0.f;
    if (p == 0) {
        const float* row = bwd_last ? (xgB + (size_t)b * 512)
                                    : (xgb + (size_t)t0 * 512);
        xi  = row[j];
        xf  = row[128 + j];
        xgv = row[256 + j];
        xo  = row[384 + j];
    }

    const float* worow = Wo_s + (size_t)tid * WO_STRIDE;
    const float* hbase = hvec + kb;

    for (int s = 0; s < nsteps; s++) {
        const int t = t0 + s * dt;

        ull aI = 0ull, aF = 0ull, aG = 0ull, aO = 0ull;
        // first half of k-range: o-gate weights from registers
#pragma unroll
        for (int q4 = 0; q4 < 8; q4++) {
            ulonglong2 hq = *reinterpret_cast<const ulonglong2*>(hbase + 4 * q4);
            aI = fma2(hq.x, Wi[2 * q4], aI);
            aF = fma2(hq.x, Wf[2 * q4], aF);
            aG = fma2(hq.x, Wg[2 * q4], aG);
            aO = fma2(hq.x, WoR[2 * q4], aO);
            aI = fma2(hq.y, Wi[2 * q4 + 1], aI);
            aF = fma2(hq.y, Wf[2 * q4 + 1], aF);
            aG = fma2(hq.y, Wg[2 * q4 + 1], aG);
            aO = fma2(hq.y, WoR[2 * q4 + 1], aO);
        }
        // second half: o-gate weights streamed from smem
#pragma unroll
        for (int q4 = 8; q4 < 16; q4++) {
            ulonglong2 hq = *reinterpret_cast<const ulonglong2*>(hbase + 4 * q4);
            ulonglong2 wq = *reinterpret_cast<const ulonglong2*>(worow + 4 * q4);
            aI = fma2(hq.x, Wi[2 * q4], aI);
            aF = fma2(hq.x, Wf[2 * q4], aF);
            aG = fma2(hq.x, Wg[2 * q4], aG);
            aO = fma2(hq.x, wq.x,       aO);
            aI = fma2(hq.y, Wi[2 * q4 + 1], aI);
            aF = fma2(hq.y, Wf[2 * q4 + 1], aF);
            aG = fma2(hq.y, Wg[2 * q4 + 1], aG);
            aO = fma2(hq.y, wq.y,           aO);
        }
        red[0 * 256 + tid] = aI;
        red[1 * 256 + tid] = aF;
        red[2 * 256 + tid] = aG;
        red[3 * 256 + tid] = aO;
        __syncthreads();

        float nxi = 0.f, nxf = 0.f, nxg = 0.f, nxo = 0.f;
        if (p == 0 && s + 1 < nsteps) {
            const size_t bse = (size_t)(t + dt) * 512;
            nxi = xgb[bse + j];
            nxf = xgb[bse + 128 + j];
            nxg = xgb[bse + 256 + j];
            nxo = xgb[bse + 384 + j];
        }

        if (p == 0) {
            float ai = hsum2(add2(red[0 * 256 + j], red[0 * 256 + 128 + j])) + xi;
            float af = hsum2(add2(red[1 * 256 + j], red[1 * 256 + 128 + j])) + xf;
            float ag = hsum2(add2(red[2 * 256 + j], red[2 * 256 + 128 + j])) + xgv;
            float ao = hsum2(add2(red[3 * 256 + j], red[3 * 256 + 128 + j])) + xo;

            float ig = sig_a(ai);
            float fg = sig_a(af);
            float og = sig_a(ao);
            c = fmaf(fg, c, ig * tanh_a(ag));
            float hn = og * tanh_a(c);

            hvec[j] = hn;
            if (!final_layer) {
                y[((size_t)b * TT + t) * 256 + d * 128 + j] = hn;
            } else if (s == nsteps - 1) {
                y[(size_t)b * 256 + d * 128 + j] = hn;
            }
        }
        __syncthreads();

        xi = nxi; xf = nxf; xgv = nxg; xo = nxo;
    }
}

// ---------------------------------------------------------------------------
// Kernel 4: linear head
// ---------------------------------------------------------------------------
__global__ void head_k(const float* __restrict__ ylast,
                       const float* __restrict__ w,
                       const float* __restrict__ bsc,
                       float* __restrict__ out) {
    int b = blockIdx.x;
    int l = threadIdx.x;
    float s = 0.f;
#pragma unroll
    for (int k = l; k < 256; k += 32) s += ylast[(size_t)b * 256 + k] * w[k];
#pragma unroll
    for (int o = 16; o; o >>= 1) s += __shfl_xor_sync(0xffffffffu, s, o);
    if (l == 0) out[b] = s + bsc[0];
}

// ---------------------------------------------------------------------------
extern "C" void kernel_launch(void* const* d_in, const int* in_sizes, int n_in,
                              void* d_out, int out_size) {
    const int*   X     = (const int*)d_in[0];
    const float* emb   = (const float*)d_in[1];
    const float* hx    = (const float*)d_in[2];
    const float* cx    = (const float*)d_in[3];
    const float* lin_w = (const float*)d_in[4];
    const float* lin_b = (const float*)d_in[5];
    const float* w_ih[3] = {(const float*)d_in[6],  (const float*)d_in[10], (const float*)d_in[14]};
    const float* w_hh[3] = {(const float*)d_in[7],  (const float*)d_in[11], (const float*)d_in[15]};
    const float* b_ih[3] = {(const float*)d_in[8],  (const float*)d_in[12], (const float*)d_in[16]};
    const float* b_hh[3] = {(const float*)d_in[9],  (const float*)d_in[13], (const float*)d_in[17]};
    float* out = (float*)d_out;

    float *xgp, *xgB, *ya, *yb, *ylast, *biasp;
    __nv_bfloat16 *xc, *wc;
    cudaGetSymbolAddress((void**)&xgp,   g_xg);
    cudaGetSymbolAddress((void**)&xgB,   g_xgB);
    cudaGetSymbolAddress((void**)&ya,    g_ya);
    cudaGetSymbolAddress((void**)&yb,    g_yb);
    cudaGetSymbolAddress((void**)&ylast, g_ylast);
    cudaGetSymbolAddress((void**)&xc,    g_xc);
    cudaGetSymbolAddress((void**)&wc,    g_wc);
    cudaGetSymbolAddress((void**)&biasp, g_bias);

    cudaFuncSetAttribute(lstm2,
                         cudaFuncAttributeMaxDynamicSharedMemorySize, LSTM2_SMEM);

    // --- layer 0 (fused embed+split) ----------------------------------------
    conv_x0<<<(MMM * 16) / 256, 256>>>(X, emb, xc);
    conv_w<<<(1024 * 128) / 256, 256>>>(w_ih[0], wc, 7);
    bias_k<<<1024 / 256, 256>>>(b_ih[0], b_hh[0], biasp);
    gemm_mma<<<dim3(8, 256), 256>>>(xc, wc, biasp, xgp, 384, 12);
    lstm2<<<128, 256, LSTM2_SMEM>>>(xgp, nullptr, w_hh[0], hx + 0 * BB * 128, cx + 0 * BB * 128, ya, 0);

    // --- layer 1 ------------------------------------------------------------
    conv_x<<<(MMM * 32) / 256, 256>>>(ya, xc);
    conv_w<<<(1024 * 256) / 256, 256>>>(w_ih[1], wc, 8);
    bias_k<<<1024 / 256, 256>>>(b_ih[1], b_hh[1], biasp);
    gemm_mma<<<dim3(8, 256), 256>>>(xc, wc, biasp, xgp, 768, 24);
    lstm2<<<128, 256, LSTM2_SMEM>>>(xgp, nullptr, w_hh[1], hx + 2 * BB * 128, cx + 2 * BB * 128, yb, 0);

    // --- layer 2 (fwd full via MMA GEMM; bwd last-t via fp32 GEMV) ----------
    conv_x<<<(MMM * 32) / 256, 256>>>(yb, xc);
    conv_w<<<(512 * 256) / 256, 256>>>(w_ih[2], wc, 8);            // d=0 rows only
    bias_k<<<512 / 256, 256>>>(b_ih[2], b_hh[2], biasp);
    gemm_mma<<<dim3(4, 256), 256>>>(xc, wc, biasp, xgp, 768, 24);
    gemv_last<<<BB, 256>>>(yb, w_ih[2], b_ih[2], b_hh[2], xgB);
    lstm2<<<128, 256, LSTM2_SMEM>>>(xgp, xgB, w_hh[2], hx + 4 * BB * 128, cx + 4 * BB * 128, ylast, 1);

    head_k<<<BB, 32>>>(ylast, lin_w, lin_b, out);
}

// round 16
// speedup vs baseline: 1.1794x; 1.1794x over previous
#include <cuda_runtime.h>
#include <cuda_bf16.h>
#include <cstdint>

typedef unsigned long long ull;

#define BB    64
#define TT    512
#define MMM   (BB * TT)

// ---------------------------------------------------------------------------
// Scratch (static __device__ arrays -- allocation-free)
// ---------------------------------------------------------------------------
__device__ float g_xg[2u * MMM * 512];
__device__ float g_xgB[BB * 512];
__device__ float g_ya[MMM * 256];
__device__ float g_yb[MMM * 256];
__device__ float g_ylast[BB * 256];
__device__ __nv_bfloat16 g_xc[(size_t)MMM * 768];   // split X  [M][3K]
__device__ __nv_bfloat16 g_wc[1024 * 768];          // split W  [N][3K]
__device__ float g_bias[1024];

// ---------------------------------------------------------------------------
// f32x2 helpers (LSTM / gemv)
// ---------------------------------------------------------------------------
__device__ __forceinline__ ull pk2(float lo, float hi) {
    ull r; asm("mov.b64 %0, {%1, %2};" : "=l"(r) : "f"(lo), "f"(hi)); return r;
}
__device__ __forceinline__ ull fma2(ull a, ull b, ull c) {
    ull d; asm("fma.rn.f32x2 %0, %1, %2, %3;" : "=l"(d) : "l"(a), "l"(b), "l"(c)); return d;
}
__device__ __forceinline__ ull add2(ull a, ull b) {
    ull d; asm("add.rn.f32x2 %0, %1, %2;" : "=l"(d) : "l"(a), "l"(b)); return d;
}
__device__ __forceinline__ float2 upk2(ull v) {
    float2 f; asm("mov.b64 {%0, %1}, %2;" : "=f"(f.x), "=f"(f.y) : "l"(v)); return f;
}
__device__ __forceinline__ float hsum2(ull v) { float2 f = upk2(v); return f.x + f.y; }

__device__ __forceinline__ float tanh_a(float x) {
    float r; asm("tanh.approx.f32 %0, %1;" : "=f"(r) : "f"(x)); return r;
}
__device__ __forceinline__ float sig_a(float x) {
    return fmaf(0.5f, tanh_a(0.5f * x), 0.5f);
}

__device__ __forceinline__ uint32_t smem_u32(const void* p) {
    uint32_t a;
    asm("{ .reg .u64 t; cvta.to.shared.u64 t, %1; cvt.u32.u64 %0, t; }" : "=r"(a) : "l"(p));
    return a;
}

// pack 8 floats -> (hi uint4, lo uint4) of bf16
__device__ __forceinline__ void split8(const float* v, uint4& hiP, uint4& loP) {
    __nv_bfloat162 h[4], l[4];
#pragma unroll
    for (int q = 0; q < 4; q++) {
        __nv_bfloat16 h0 = __float2bfloat16(v[2 * q]);
        __nv_bfloat16 h1 = __float2bfloat16(v[2 * q + 1]);
        __nv_bfloat16 l0 = __float2bfloat16(v[2 * q]     - __bfloat162float(h0));
        __nv_bfloat16 l1 = __float2bfloat16(v[2 * q + 1] - __bfloat162float(h1));
        h[q] = __nv_bfloat162(h0, h1);
        l[q] = __nv_bfloat162(l0, l1);
    }
    hiP = *reinterpret_cast<uint4*>(h);
    loP = *reinterpret_cast<uint4*>(l);
}

// ---------------------------------------------------------------------------
// conv_x0: fused embedding gather + bf16 split for layer 0 (K=128).
// ---------------------------------------------------------------------------
__global__ void conv_x0(const int* __restrict__ Xtok,
                        const float* __restrict__ emb,
                        __nv_bfloat16* __restrict__ out) {
    int i = blockIdx.x * 256 + threadIdx.x;     // MMM*16 threads
    int m  = i >> 4;
    int k8 = (i & 15) << 3;
    int tok = Xtok[m];
    float v[8];
    *reinterpret_cast<float4*>(v)     = *reinterpret_cast<const float4*>(&emb[(size_t)tok * 128 + k8]);
    *reinterpret_cast<float4*>(v + 4) = *reinterpret_cast<const float4*>(&emb[(size_t)tok * 128 + k8 + 4]);
    uint4 hiP, loP;
    split8(v, hiP, loP);
    __nv_bfloat16* base = out + (size_t)m * 384;
    *reinterpret_cast<uint4*>(base + k8)       = hiP;
    *reinterpret_cast<uint4*>(base + 128 + k8) = hiP;
    *reinterpret_cast<uint4*>(base + 256 + k8) = loP;
}

// ---------------------------------------------------------------------------
// conv_x: vectorized fp32 [M][256] -> bf16 split [M][768]  (layers 1,2)
// ---------------------------------------------------------------------------
__global__ void conv_x(const float* __restrict__ in, __nv_bfloat16* __restrict__ out) {
    int i = blockIdx.x * 256 + threadIdx.x;     // MMM*32 threads
    int m  = i >> 5;
    int k8 = (i & 31) << 3;
    float v[8];
    *reinterpret_cast<float4*>(v)     = *reinterpret_cast<const float4*>(&in[(size_t)m * 256 + k8]);
    *reinterpret_cast<float4*>(v + 4) = *reinterpret_cast<const float4*>(&in[(size_t)m * 256 + k8 + 4]);
    uint4 hiP, loP;
    split8(v, hiP, loP);
    __nv_bfloat16* base = out + (size_t)m * 768;
    *reinterpret_cast<uint4*>(base + k8)       = hiP;
    *reinterpret_cast<uint4*>(base + 256 + k8) = hiP;
    *reinterpret_cast<uint4*>(base + 512 + k8) = loP;
}

// ---------------------------------------------------------------------------
// conv_w: fp32 [N][K] -> bf16 split [N][3K] = [hi | lo | hi]  (scalar, tiny)
// ---------------------------------------------------------------------------
__global__ void conv_w(const float* __restrict__ in, __nv_bfloat16* __restrict__ out,
                       int kshift) {
    int i = blockIdx.x * 256 + threadIdx.x;
    int K = 1 << kshift;
    int n = i >> kshift;
    int k = i & (K - 1);
    float v = in[i];
    __nv_bfloat16 hi = __float2bfloat16(v);
    __nv_bfloat16 lo = __float2bfloat16(v - __bfloat162float(hi));
    size_t base = (size_t)n * 3 * K;
    out[base + k]         = hi;
    out[base + K + k]     = lo;
    out[base + 2 * K + k] = hi;
}

__global__ void bias_k(const float* __restrict__ bi, const float* __restrict__ bh,
                       float* __restrict__ out) {
    int i = blockIdx.x * 256 + threadIdx.x;
    out[i] = bi[i] + bh[i];
}

// ---------------------------------------------------------------------------
// Kernel 2: tensor-core GEMM via mma.sync (bf16 -> f32)
// ---------------------------------------------------------------------------
#define TILE_BYTES 10240   /* 128 rows x 80 B */

#define LDSM4(r0, r1, r2, r3, addr) \
    asm volatile("ldmatrix.sync.aligned.m8n8.x4.shared.b16 {%0,%1,%2,%3}, [%4];" \
        : "=r"(r0), "=r"(r1), "=r"(r2), "=r"(r3) : "r"(addr))

#define MMA16816(d, a, b0, b1) \
    asm volatile("mma.sync.aligned.m16n8k16.row.col.f32.bf16.bf16.f32 " \
        "{%0,%1,%2,%3}, {%4,%5,%6,%7}, {%8,%9}, {%0,%1,%2,%3};" \
        : "+f"((d)[0]), "+f"((d)[1]), "+f"((d)[2]), "+f"((d)[3]) \
        : "r"((a)[0]), "r"((a)[1]), "r"((a)[2]), "r"((a)[3]), "r"(b0), "r"(b1))

__global__ __launch_bounds__(256, 2)
void gemm_mma(const __nv_bfloat16* __restrict__ Xc,
              const __nv_bfloat16* __restrict__ Wc,
              const float* __restrict__ bias,
              float* __restrict__ C,
              int K3, int NC) {
    __shared__ __align__(16) char smA[2][TILE_BYTES];
    __shared__ __align__(16) char smB[2][TILE_BYTES];

    const int tid = threadIdx.x;
    const int w  = tid >> 5, L = tid & 31;
    const int wm = w >> 2,  wn = w & 3;
    const int g  = L >> 3,  r  = L & 7;
    const int m0 = blockIdx.y * 128, n0 = blockIdx.x * 128;

    const uint32_t aSB = smem_u32(smA);
    const uint32_t bSB = smem_u32(smB);

    uint32_t aoff[4][2], boff[2][2];
#pragma unroll
    for (int i = 0; i < 4; i++)
#pragma unroll
        for (int h = 0; h < 2; h++)
            aoff[i][h] = (uint32_t)((wm * 64 + i * 16 + (g & 1) * 8 + r) * 80
                                    + (g >> 1) * 16 + h * 32);
#pragma unroll
    for (int jj = 0; jj < 2; jj++)
#pragma unroll
        for (int h = 0; h < 2; h++)
            boff[jj][h] = (uint32_t)((wn * 32 + jj * 16 + (g >> 1) * 8 + r) * 80
                                     + (g & 1) * 16 + h * 32);

    const int s0 = tid * 2, s1 = tid * 2 + 1;
    const int row0 = s0 >> 2, u0 = s0 & 3;
    const int row1 = s1 >> 2, u1 = s1 & 3;

    float acc[16][4];
#pragma unroll
    for (int i = 0; i < 16; i++)
#pragma unroll
        for (int q = 0; q < 4; q++) acc[i][q] = 0.f;

    uint4 ar0, ar1, br0, br1;

#define LDG_CHUNK(c)                                                            \
    {                                                                           \
        ar0 = *reinterpret_cast<const uint4*>(Xc + (size_t)(m0 + row0) * K3 + (c) * 32 + u0 * 8); \
        ar1 = *reinterpret_cast<const uint4*>(Xc + (size_t)(m0 + row1) * K3 + (c) * 32 + u1 * 8); \
        br0 = *reinterpret_cast<const uint4*>(Wc + (size_t)(n0 + row0) * K3 + (c) * 32 + u0 * 8); \
        br1 = *reinterpret_cast<const uint4*>(Wc + (size_t)(n0 + row1) * K3 + (c) * 32 + u1 * 8); \
    }

#define STS_CHUNK(b)                                                            \
    {                                                                           \
        *reinterpret_cast<uint4*>(smA[b] + row0 * 80 + u0 * 16) = ar0;          \
        *reinterpret_cast<uint4*>(smA[b] + row1 * 80 + u1 * 16) = ar1;          \
        *reinterpret_cast<uint4*>(smB[b] + row0 * 80 + u0 * 16) = br0;          \
        *reinterpret_cast<uint4*>(smB[b] + row1 * 80 + u1 * 16) = br1;          \
    }

    LDG_CHUNK(0);
    STS_CHUNK(0);
    __syncthreads();
    if (NC > 1) LDG_CHUNK(1);

    for (int c = 0; c < NC; c++) {
        const int b = c & 1;
        const uint32_t aB = aSB + b * TILE_BYTES;
        const uint32_t bO = bSB + b * TILE_BYTES;
#pragma unroll
        for (int h = 0; h < 2; h++) {
            uint32_t af[4][4], bf2[2][4];
#pragma unroll
            for (int i = 0; i < 4; i++)
                LDSM4(af[i][0], af[i][1], af[i][2], af[i][3], aB + aoff[i][h]);
#pragma unroll
            for (int jj = 0; jj < 2; jj++)
                LDSM4(bf2[jj][0], bf2[jj][1], bf2[jj][2], bf2[jj][3], bO + boff[jj][h]);
#pragma unroll
            for (int i = 0; i < 4; i++) {
#pragma unroll
                for (int nj = 0; nj < 4; nj++) {
                    MMA16816(acc[i * 4 + nj], af[i],
                             bf2[nj >> 1][(nj & 1) * 2], bf2[nj >> 1][(nj & 1) * 2 + 1]);
                }
            }
        }
        if (c + 1 < NC) {
            STS_CHUNK((c + 1) & 1);
            if (c + 2 < NC) LDG_CHUNK(c + 2);
            __syncthreads();
        }
    }

#pragma unroll
    for (int i = 0; i < 4; i++) {
#pragma unroll
        for (int nj = 0; nj < 4; nj++) {
            const int mg = m0 + wm * 64 + i * 16 + (L >> 2);
            const int ng = n0 + wn * 32 + nj * 8 + (L & 3) * 2;
            const int dd = ng >> 9;
            const int col = ng & 511;
            const float bv0 = bias[ng], bv1 = bias[ng + 1];
            float* Cd = C + (size_t)dd * MMM * 512;
            float* p0 = &Cd[(size_t)mg * 512 + col];
            float* p1 = &Cd[(size_t)(mg + 8) * 512 + col];
            *reinterpret_cast<float2*>(p0) =
                make_float2(acc[i * 4 + nj][0] + bv0, acc[i * 4 + nj][1] + bv1);
            *reinterpret_cast<float2*>(p1) =
                make_float2(acc[i * 4 + nj][2] + bv0, acc[i * 4 + nj][3] + bv1);
        }
    }
}

// ---------------------------------------------------------------------------
// Kernel 2b: layer-2 backward last-timestep GEMV (fp32, exact)
// ---------------------------------------------------------------------------
__global__ __launch_bounds__(256)
void gemv_last(const float* __restrict__ y,
               const float* __restrict__ Wfull,
               const float* __restrict__ bi,
               const float* __restrict__ bh,
               float* __restrict__ out) {
    __shared__ float xr[256];
    const int b = blockIdx.x;
    const float* x = y + ((size_t)b * TT + (TT - 1)) * 256;
    xr[threadIdx.x] = x[threadIdx.x];
    __syncthreads();
#pragma unroll
    for (int nn = 0; nn < 2; nn++) {
        int n = threadIdx.x + nn * 256;
        const float* wr = Wfull + (size_t)(512 + n) * 256;
        ull s2 = 0ull;
        const ull* xp = reinterpret_cast<const ull*>(xr);
        const ull* wp = reinterpret_cast<const ull*>(wr);
#pragma unroll
        for (int k = 0; k < 128; k++) s2 = fma2(xp[k], wp[k], s2);
        out[(size_t)b * 512 + n] = hsum2(s2) + bi[512 + n] + bh[512 + n];
    }
}

// ---------------------------------------------------------------------------
// Kernel 3: LSTM recurrence — EXACT R13 version (no WoR registers; o-gate
// fully streamed from smem; i,f,g in 96 ull registers).
// ---------------------------------------------------------------------------
#define WO_STRIDE 68
#define WO_FLOATS (256 * WO_STRIDE)
#define RED_OFF   WO_FLOATS
#define HV_OFF    (WO_FLOATS + 2048)
#define LSTM2_SMEM ((HV_OFF + 160) * 4)

__global__ __launch_bounds__(256, 1)
void lstm2(const float* __restrict__ xg,
           const float* __restrict__ xgB,
           const float* __restrict__ whh,
           const float* __restrict__ hx0,
           const float* __restrict__ cx0,
           float* __restrict__ y,
           int final_layer) {
    extern __shared__ float sm[];
    float* Wo_s = sm;
    ull*   red  = reinterpret_cast<ull*>(sm + RED_OFF);
    float* hvec = sm + HV_OFF;

    const int tid = threadIdx.x;
    const int j   = tid & 127;
    const int p   = tid >> 7;
    const int d   = blockIdx.x >> 6;
    const int b   = blockIdx.x & 63;
    const int kb  = p << 6;

    const float* W = whh + (size_t)d * 512 * 128;

    for (int idx = tid; idx < 128 * 128; idx += 256) {
        int rr = idx >> 7, k = idx & 127;
        float v = W[(size_t)(384 + rr) * 128 + k];
        Wo_s[((k >> 6) * 128 + rr) * WO_STRIDE + (k & 63)] = v;
    }

    ull Wi[32], Wf[32], Wg[32];
    {
        const float2* ri = reinterpret_cast<const float2*>(W + (size_t)(0   + j) * 128 + kb);
        const float2* rf = reinterpret_cast<const float2*>(W + (size_t)(128 + j) * 128 + kb);
        const float2* rg = reinterpret_cast<const float2*>(W + (size_t)(256 + j) * 128 + kb);
#pragma unroll
        for (int q = 0; q < 32; q++) {
            float2 a = ri[q]; Wi[q] = pk2(a.x, a.y);
            float2 f = rf[q]; Wf[q] = pk2(f.x, f.y);
            float2 gg = rg[q]; Wg[q] = pk2(gg.x, gg.y);
        }
    }

    float c = cx0[(size_t)(d * 64 + b) * 128 + j];
    if (tid < 128) hvec[tid] = hx0[(size_t)(d * 64 + b) * 128 + tid];
    __syncthreads();

    const int t0 = d ? (TT - 1) : 0;
    const int dt = d ? -1 : 1;
    const bool bwd_last = (final_layer && d);
    const int nsteps = bwd_last ? 1 : TT;
    const float* xgb = xg + ((size_t)d * MMM + (size_t)b * TT) * 512;

    float xi = 0.f, xf = 0.f, xgv = 0.f, xo = 0.f;
    if (p == 0) {
        const float* row = bwd_last ? (xgB + (size_t)b * 512)
                                    : (xgb + (size_t)t0 * 512);
        xi  = row[j];
        xf  = row[128 + j];
        xgv = row[256 + j];
        xo  = row[384 + j];
    }

    const float* worow = Wo_s + (size_t)tid * WO_STRIDE;
    const float* hbase = hvec + kb;

    for (int s = 0; s < nsteps; s++) {
        const int t = t0 + s * dt;

        ull aI = 0ull, aF = 0ull, aG = 0ull, aO = 0ull;
#pragma unroll
        for (int q4 = 0; q4 < 16; q4++) {
            ulonglong2 hq = *reinterpret_cast<const ulonglong2*>(hbase + 4 * q4);
            ulonglong2 wq = *reinterpret_cast<const ulonglong2*>(worow + 4 * q4);
            aI = fma2(hq.x, Wi[2 * q4], aI);
            aF = fma2(hq.x, Wf[2 * q4], aF);
            aG = fma2(hq.x, Wg[2 * q4], aG);
            aO = fma2(hq.x, wq.x,       aO);
            aI = fma2(hq.y, Wi[2 * q4 + 1], aI);
            aF = fma2(hq.y, Wf[2 * q4 + 1], aF);
            aG = fma2(hq.y, Wg[2 * q4 + 1], aG);
            aO = fma2(hq.y, wq.y,           aO);
        }
        red[0 * 256 + tid] = aI;
        red[1 * 256 + tid] = aF;
        red[2 * 256 + tid] = aG;
        red[3 * 256 + tid] = aO;
        __syncthreads();

        float nxi = 0.f, nxf = 0.f, nxg = 0.f, nxo = 0.f;
        if (p == 0 && s + 1 < nsteps) {
            const size_t bse = (size_t)(t + dt) * 512;
            nxi = xgb[bse + j];
            nxf = xgb[bse + 128 + j];
            nxg = xgb[bse + 256 + j];
            nxo = xgb[bse + 384 + j];
        }

        if (p == 0) {
            float ai = hsum2(add2(red[0 * 256 + j], red[0 * 256 + 128 + j])) + xi;
            float af = hsum2(add2(red[1 * 256 + j], red[1 * 256 + 128 + j])) + xf;
            float ag = hsum2(add2(red[2 * 256 + j], red[2 * 256 + 128 + j])) + xgv;
            float ao = hsum2(add2(red[3 * 256 + j], red[3 * 256 + 128 + j])) + xo;

            float ig = sig_a(ai);
            float fg = sig_a(af);
            float og = sig_a(ao);
            c = fmaf(fg, c, ig * tanh_a(ag));
            float hn = og * tanh_a(c);

            hvec[j] = hn;
            if (!final_layer) {
                y[((size_t)b * TT + t) * 256 + d * 128 + j] = hn;
            } else if (s == nsteps - 1) {
                y[(size_t)b * 256 + d * 128 + j] = hn;
            }
        }
        __syncthreads();

        xi = nxi; xf = nxf; xgv = nxg; xo = nxo;
    }
}

// ---------------------------------------------------------------------------
// Kernel 4: linear head
// ---------------------------------------------------------------------------
__global__ void head_k(const float* __restrict__ ylast,
                       const float* __restrict__ w,
                       const float* __restrict__ bsc,
                       float* __restrict__ out) {
    int b = blockIdx.x;
    int l = threadIdx.x;
    float s = 0.f;
#pragma unroll
    for (int k = l; k < 256; k += 32) s += ylast[(size_t)b * 256 + k] * w[k];
#pragma unroll
    for (int o = 16; o; o >>= 1) s += __shfl_xor_sync(0xffffffffu, s, o);
    if (l == 0) out[b] = s + bsc[0];
}

// ---------------------------------------------------------------------------
extern "C" void kernel_launch(void* const* d_in, const int* in_sizes, int n_in,
                              void* d_out, int out_size) {
    const int*   X     = (const int*)d_in[0];
    const float* emb   = (const float*)d_in[1];
    const float* hx    = (const float*)d_in[2];
    const float* cx    = (const float*)d_in[3];
    const float* lin_w = (const float*)d_in[4];
    const float* lin_b = (const float*)d_in[5];
    const float* w_ih[3] = {(const float*)d_in[6],  (const float*)d_in[10], (const float*)d_in[14]};
    const float* w_hh[3] = {(const float*)d_in[7],  (const float*)d_in[11], (const float*)d_in[15]};
    const float* b_ih[3] = {(const float*)d_in[8],  (const float*)d_in[12], (const float*)d_in[16]};
    const float* b_hh[3] = {(const float*)d_in[9],  (const float*)d_in[13], (const float*)d_in[17]};
    float* out = (float*)d_out;

    float *xgp, *xgB, *ya, *yb, *ylast, *biasp;
    __nv_bfloat16 *xc, *wc;
    cudaGetSymbolAddress((void**)&xgp,   g_xg);
    cudaGetSymbolAddress((void**)&xgB,   g_xgB);
    cudaGetSymbolAddress((void**)&ya,    g_ya);
    cudaGetSymbolAddress((void**)&yb,    g_yb);
    cudaGetSymbolAddress((void**)&ylast, g_ylast);
    cudaGetSymbolAddress((void**)&xc,    g_xc);
    cudaGetSymbolAddress((void**)&wc,    g_wc);
    cudaGetSymbolAddress((void**)&biasp, g_bias);

    cudaFuncSetAttribute(lstm2,
                         cudaFuncAttributeMaxDynamicSharedMemorySize, LSTM2_SMEM);

    // --- layer 0 (fused embed+split) ----------------------------------------
    conv_x0<<<(MMM * 16) / 256, 256>>>(X, emb, xc);
    conv_w<<<(1024 * 128) / 256, 256>>>(w_ih[0], wc, 7);
    bias_k<<<1024 / 256, 256>>>(b_ih[0], b_hh[0], biasp);
    gemm_mma<<<dim3(8, 256), 256>>>(xc, wc, biasp, xgp, 384, 12);
    lstm2<<<128, 256, LSTM2_SMEM>>>(xgp, nullptr, w_hh[0], hx + 0 * BB * 128, cx + 0 * BB * 128, ya, 0);

    // --- layer 1 ------------------------------------------------------------
    conv_x<<<(MMM * 32) / 256, 256>>>(ya, xc);
    conv_w<<<(1024 * 256) / 256, 256>>>(w_ih[1], wc, 8);
    bias_k<<<1024 / 256, 256>>>(b_ih[1], b_hh[1], biasp);
    gemm_mma<<<dim3(8, 256), 256>>>(xc, wc, biasp, xgp, 768, 24);
    lstm2<<<128, 256, LSTM2_SMEM>>>(xgp, nullptr, w_hh[1], hx + 2 * BB * 128, cx + 2 * BB * 128, yb, 0);

    // --- layer 2 (fwd full via MMA GEMM; bwd last-t via fp32 GEMV) ----------
    conv_x<<<(MMM * 32) / 256, 256>>>(yb, xc);
    conv_w<<<(512 * 256) / 256, 256>>>(w_ih[2], wc, 8);            // d=0 rows only
    bias_k<<<512 / 256, 256>>>(b_ih[2], b_hh[2], biasp);
    gemm_mma<<<dim3(4, 256), 256>>>(xc, wc, biasp, xgp, 768, 24);
    gemv_last<<<BB, 256>>>(yb, w_ih[2], b_ih[2], b_hh[2], xgB);
    lstm2<<<128, 256, LSTM2_SMEM>>>(xgp, xgB, w_hh[2], hx + 4 * BB * 128, cx + 4 * BB * 128, ylast, 1);

    head_k<<<BB, 32>>>(ylast, lin_w, lin_b, out);
}